// round 12
// baseline (speedup 1.0000x reference)
#include <cuda_runtime.h>
#include <cuda_fp16.h>

#define NN      256     // neurons (post)
#define NI      128     // sensory inputs
#define BATCH   1024
#define UNFOLDS 6
#define NB      8       // batch rows per CTA = 4 half2 pairs (128*8 = 1024 exact)
#define NPAIR   4
#define GRID    128
#define NT      512     // 2 groups of 256; group g reduces half the pre range
#define CHUNK   4       // j's per fp16 accumulator before fp32 flush

// Recurrent weights fp16 (duplicated half2 lanes), c split hi+lo for accuracy:
//   z = a*v + c_hi + c_lo,  a = sigma/2, c = -sigma*mu/2, p = W*erev/2.
//   q = W/2 = |p| (erev = +-1), recovered via __habs2 -- no storage needed.
// sigmoid(sigma*(v-mu)) = 0.5 + 0.5*tanh(z); constant halves folded into
// g_knum/g_kden (fp32, from raw inputs). Sensory pass fully fp32.
struct alignas(16) WH { __half2 a, chi, clo, p; };

__device__ WH     gh_rec[NN * NN];   // recurrent, [pre j][post n]
__device__ float4 g_senf[NI * NN];   // sensory fp32: (a, c, p, q)
__device__ float  g_knum[NN];        // gleak*vleak + sum over pre of P (fp32)
__device__ float  g_kden[NN];        // cm + gleak + sum over pre of Q (fp32)

__device__ __forceinline__ float tanh_fast(float x) {
    float y;
    asm("tanh.approx.f32 %0, %1;" : "=f"(y) : "f"(x));
    return y;
}
__device__ __forceinline__ __half2 tanh2_fast(__half2 x) {
    __half2 y;
    asm("tanh.approx.f16x2 %0, %1;"
        : "=r"(*reinterpret_cast<unsigned*>(&y))
        : "r"(*reinterpret_cast<unsigned*>(&x)));
    return y;
}
__device__ __forceinline__ __half2 u2h(unsigned v) {
    __half2 h;
    *reinterpret_cast<unsigned*>(&h) = v;
    return h;
}

// ---------------------------------------------------------------------------
// Prep kernels
// ---------------------------------------------------------------------------
__global__ void pack_rec_kernel(const float* __restrict__ mu,
                                const float* __restrict__ sigma,
                                const float* __restrict__ W,
                                const float* __restrict__ erev) {
    int idx = blockIdx.x * NN + threadIdx.x;   // j * NN + n
    float a = 0.5f * sigma[idx];
    float m = mu[idx];
    float q = 0.5f * W[idx];
    float e = erev[idx];
    float c = -a * m;
    __half chi = __float2half_rn(c);
    float clo = c - __half2float(chi);
    WH w;
    w.a   = __float2half2_rn(a);
    w.chi = __half2half2(chi);
    w.clo = __float2half2_rn(clo);
    w.p   = __float2half2_rn(q * e);
    gh_rec[idx] = w;
}

__global__ void pack_sen_kernel(const float* __restrict__ smu,
                                const float* __restrict__ ssigma,
                                const float* __restrict__ sW,
                                const float* __restrict__ serev) {
    int idx = blockIdx.x * NN + threadIdx.x;   // i * NN + n
    float a = 0.5f * ssigma[idx];
    float m = smu[idx];
    float q = 0.5f * sW[idx];
    float e = serev[idx];
    g_senf[idx] = make_float4(a, -a * m, q * e, q);
}

__global__ void reduce_k_kernel(const float* __restrict__ W,
                                const float* __restrict__ erev,
                                const float* __restrict__ sW,
                                const float* __restrict__ serev,
                                const float* __restrict__ vleak,
                                const float* __restrict__ gleak,
                                const float* __restrict__ cm_t) {
    __shared__ float rp[128];
    __shared__ float rq[128];
    int n = blockIdx.x;
    int t = threadIdx.x;
    float sp = 0.0f, sq = 0.0f;
    for (int j = t; j < NN; j += 128) {
        float q = 0.5f * W[j * NN + n];
        sp += q * erev[j * NN + n];
        sq += q;
    }
    for (int i = t; i < NI; i += 128) {
        float q = 0.5f * sW[i * NN + n];
        sp += q * serev[i * NN + n];
        sq += q;
    }
    rp[t] = sp; rq[t] = sq;
    __syncthreads();
    for (int s = 64; s > 0; s >>= 1) {
        if (t < s) { rp[t] += rp[t + s]; rq[t] += rq[t + s]; }
        __syncthreads();
    }
    if (t == 0) {
        g_knum[n] = fmaf(gleak[n], vleak[n], rp[0]);
        g_kden[n] = cm_t[n] + gleak[n] + rq[0];
    }
}

// ---------------------------------------------------------------------------
// Main: 1 CTA/SM (GRID=128), 512 threads = 2 groups x 256. Thread owns output
// neuron n = tid&255; group g = tid>>8 reduces half the presynaptic range.
// 8 batch rows as 4 half2 pairs; one LDG.128 (weights) + one LDS.128 (state)
// per j serves all 4 pairs. fp16 accumulators flushed to fp32 every CHUNK j's.
// Sensory pass, state, division, output all fp32.
// ---------------------------------------------------------------------------
__global__ __launch_bounds__(NT, 1) void liquid_main_kernel(
    const float* __restrict__ inputs,
    const float* __restrict__ state,
    const float* __restrict__ map_w,
    const float* __restrict__ map_b,
    const float* __restrict__ cm_t,
    float* __restrict__ out,
    int copies) {

    __shared__ float   sxf[NB][NI];                // mapped inputs (fp32)
    __shared__ alignas(16) __half2 sv2[NN][NPAIR]; // v state pairs: [j][pair]
    __shared__ float   pnum[NB][NN];               // group-1 partial numerators
    __shared__ float   pden[NB][NN];               // group-1 partial denominators

    const int tid = threadIdx.x;
    const int n   = tid & (NN - 1);
    const int g   = tid >> 8;            // 0 or 1
    const int r0  = blockIdx.x * NB;

    // Load + map inputs (fp32)
    for (int idx = tid; idx < NB * NI; idx += NT) {
        int bb = idx >> 7;
        int i  = idx & (NI - 1);
        sxf[bb][i] = fmaf(inputs[(r0 + bb) * NI + i], map_w[i], map_b[i]);
    }
    // Load v state into half2 pairs: sv2[j][p] = (v[2p][j], v[2p+1][j])
    for (int idx = tid; idx < NN * NPAIR; idx += NT) {
        int j = idx >> 2;
        int p = idx & 3;
        sv2[j][p] = __floats2half2_rn(state[(r0 + 2 * p)     * NN + j],
                                      state[(r0 + 2 * p + 1) * NN + j]);
    }
    // fp32 state registers (group 0 uses them for cm*v and division)
    float vf[NB];
    #pragma unroll
    for (int bb = 0; bb < NB; bb++) vf[bb] = state[(r0 + bb) * NN + n];
    __syncthreads();

    const float cmn = cm_t[n];

    // ---- Sensory pass (fp32): group g reduces i in [g*64, g*64+64) ----
    float snum[NB], sden[NB];
    #pragma unroll
    for (int bb = 0; bb < NB; bb++) { snum[bb] = 0.0f; sden[bb] = 0.0f; }
    {
        const int ib = g * (NI / 2);
        #pragma unroll 2
        for (int ii = 0; ii < NI / 2; ii++) {
            float4 w = g_senf[(ib + ii) * NN + n];
            #pragma unroll
            for (int bb = 0; bb < NB; bb++) {
                float z = fmaf(w.x, sxf[bb][ib + ii], w.y);
                float t = tanh_fast(z);
                snum[bb] = fmaf(w.z, t, snum[bb]);
                sden[bb] = fmaf(w.w, t, sden[bb]);
            }
        }
    }
    if (g == 1) {
        #pragma unroll
        for (int bb = 0; bb < NB; bb++) { pnum[bb][n] = snum[bb]; pden[bb][n] = sden[bb]; }
    }
    __syncthreads();
    if (g == 0) {
        const float kn = g_knum[n];
        const float kd = g_kden[n];
        #pragma unroll
        for (int bb = 0; bb < NB; bb++) {
            snum[bb] += pnum[bb][n] + kn;
            sden[bb] += pden[bb][n] + kd;
        }
    }
    __syncthreads();   // pnum/pden free for reuse

    const int jb = g * (NN / 2);

    // ---- Unfold loop (fp16x2 recurrent reduction, 4 pairs) ----
    for (int step = 0; step < UNFOLDS; step++) {
        float num[NB], den[NB];
        if (g == 0) {
            #pragma unroll
            for (int bb = 0; bb < NB; bb++) {
                num[bb] = fmaf(cmn, vf[bb], snum[bb]);
                den[bb] = sden[bb];
            }
        } else {
            #pragma unroll
            for (int bb = 0; bb < NB; bb++) { num[bb] = 0.0f; den[bb] = 0.0f; }
        }

        for (int ch = 0; ch < (NN / 2) / CHUNK; ch++) {
            __half2 hn[NPAIR], hd[NPAIR];
            #pragma unroll
            for (int p = 0; p < NPAIR; p++) {
                hn[p] = __float2half2_rn(0.0f);
                hd[p] = __float2half2_rn(0.0f);
            }
            #pragma unroll
            for (int cj = 0; cj < CHUNK; cj++) {
                int j = jb + ch * CHUNK + cj;
                uint4 u = *reinterpret_cast<const uint4*>(gh_rec + j * NN + n);
                __half2 wa = u2h(u.x), wchi = u2h(u.y), wclo = u2h(u.z), wp = u2h(u.w);
                __half2 wq = __habs2(wp);     // q = |p| since erev = +-1
                uint4 vv = *reinterpret_cast<const uint4*>(&sv2[j][0]);
                __half2 v0 = u2h(vv.x), v1 = u2h(vv.y), v2 = u2h(vv.z), v3 = u2h(vv.w);
                __half2 t;
                t = tanh2_fast(__hadd2(__hfma2(wa, v0, wchi), wclo));
                hn[0] = __hfma2(wp, t, hn[0]);  hd[0] = __hfma2(wq, t, hd[0]);
                t = tanh2_fast(__hadd2(__hfma2(wa, v1, wchi), wclo));
                hn[1] = __hfma2(wp, t, hn[1]);  hd[1] = __hfma2(wq, t, hd[1]);
                t = tanh2_fast(__hadd2(__hfma2(wa, v2, wchi), wclo));
                hn[2] = __hfma2(wp, t, hn[2]);  hd[2] = __hfma2(wq, t, hd[2]);
                t = tanh2_fast(__hadd2(__hfma2(wa, v3, wchi), wclo));
                hn[3] = __hfma2(wp, t, hn[3]);  hd[3] = __hfma2(wq, t, hd[3]);
            }
            #pragma unroll
            for (int p = 0; p < NPAIR; p++) {
                num[2 * p]     += __low2float(hn[p]);
                num[2 * p + 1] += __high2float(hn[p]);
                den[2 * p]     += __low2float(hd[p]);
                den[2 * p + 1] += __high2float(hd[p]);
            }
        }

        if (g == 1) {
            #pragma unroll
            for (int bb = 0; bb < NB; bb++) { pnum[bb][n] = num[bb]; pden[bb][n] = den[bb]; }
        }
        __syncthreads();   // partials visible; all sv2 reads complete
        if (g == 0) {
            #pragma unroll
            for (int bb = 0; bb < NB; bb++) {
                float nu = num[bb] + pnum[bb][n];
                float de = den[bb] + pden[bb][n];
                vf[bb] = __fdividef(nu, de);
            }
            sv2[n][0] = __floats2half2_rn(vf[0], vf[1]);
            sv2[n][1] = __floats2half2_rn(vf[2], vf[3]);
            sv2[n][2] = __floats2half2_rn(vf[4], vf[5]);
            sv2[n][3] = __floats2half2_rn(vf[6], vf[7]);
        }
        __syncthreads();
    }

    // ---- Output (reference returns (v, v) -> possibly 2 copies) ----
    if (g == 0) {
        #pragma unroll
        for (int bb = 0; bb < NB; bb++) {
            int row = r0 + bb;
            for (int c = 0; c < copies; c++)
                out[c * (BATCH * NN) + row * NN + n] = vf[bb];
        }
    }
}

// ---------------------------------------------------------------------------
extern "C" void kernel_launch(void* const* d_in, const int* in_sizes, int n_in,
                              void* d_out, int out_size) {
    const float* inputs = (const float*)d_in[0];
    const float* state  = (const float*)d_in[1];
    const float* map_w  = (const float*)d_in[2];
    const float* map_b  = (const float*)d_in[3];
    const float* smu    = (const float*)d_in[4];
    const float* ssig   = (const float*)d_in[5];
    const float* sW     = (const float*)d_in[6];
    const float* serev  = (const float*)d_in[7];
    const float* mu     = (const float*)d_in[8];
    const float* sigma  = (const float*)d_in[9];
    const float* W      = (const float*)d_in[10];
    const float* erev   = (const float*)d_in[11];
    const float* vleak  = (const float*)d_in[12];
    const float* gleak  = (const float*)d_in[13];
    const float* cm     = (const float*)d_in[14];

    int copies = out_size / (BATCH * NN);
    if (copies < 1) copies = 1;

    pack_rec_kernel<<<NN, NN>>>(mu, sigma, W, erev);
    pack_sen_kernel<<<NI, NN>>>(smu, ssig, sW, serev);
    reduce_k_kernel<<<NN, 128>>>(W, erev, sW, serev, vleak, gleak, cm);
    liquid_main_kernel<<<GRID, NT>>>(inputs, state, map_w, map_b, cm,
                                     (float*)d_out, copies);
}

// round 13
// speedup vs baseline: 1.0625x; 1.0625x over previous
#include <cuda_runtime.h>
#include <cuda_fp16.h>

#define NN      256     // neurons (post)
#define NI      128     // sensory inputs
#define BATCH   1024
#define UNFOLDS 6
#define NB      8       // batch rows per CTA = 4 half2 pairs (128*8 = 1024 exact)
#define NPAIR   4
#define GRID    128
#define NT      768     // 3 groups of 256; group g reduces a third of the pre range
#define CHUNK   4       // j's per fp16 accumulator before fp32 flush

// Recurrent weights fp16 (duplicated half2 lanes), c split hi+lo for accuracy:
//   z = a*v + c_hi + c_lo,  a = sigma/2, c = -sigma*mu/2, p = W*erev/2.
//   q = W/2 = |p| (erev = +-1), recovered via __habs2 -- no storage needed.
// sigmoid(sigma*(v-mu)) = 0.5 + 0.5*tanh(z); constant halves folded into
// g_knum/g_kden (fp32, from raw inputs). Sensory pass fully fp32.
struct alignas(16) WH { __half2 a, chi, clo, p; };

__device__ WH     gh_rec[NN * NN];   // recurrent, [pre j][post n]
__device__ float4 g_senf[NI * NN];   // sensory fp32: (a, c, p, q)
__device__ float  g_knum[NN];        // gleak*vleak + sum over pre of P (fp32)
__device__ float  g_kden[NN];        // cm + gleak + sum over pre of Q (fp32)

__device__ __forceinline__ float tanh_fast(float x) {
    float y;
    asm("tanh.approx.f32 %0, %1;" : "=f"(y) : "f"(x));
    return y;
}
__device__ __forceinline__ __half2 tanh2_fast(__half2 x) {
    __half2 y;
    asm("tanh.approx.f16x2 %0, %1;"
        : "=r"(*reinterpret_cast<unsigned*>(&y))
        : "r"(*reinterpret_cast<unsigned*>(&x)));
    return y;
}
__device__ __forceinline__ __half2 u2h(unsigned v) {
    __half2 h;
    *reinterpret_cast<unsigned*>(&h) = v;
    return h;
}

// ---------------------------------------------------------------------------
// Prep kernels
// ---------------------------------------------------------------------------
__global__ void pack_rec_kernel(const float* __restrict__ mu,
                                const float* __restrict__ sigma,
                                const float* __restrict__ W,
                                const float* __restrict__ erev) {
    int idx = blockIdx.x * NN + threadIdx.x;   // j * NN + n
    float a = 0.5f * sigma[idx];
    float m = mu[idx];
    float q = 0.5f * W[idx];
    float e = erev[idx];
    float c = -a * m;
    __half chi = __float2half_rn(c);
    float clo = c - __half2float(chi);
    WH w;
    w.a   = __float2half2_rn(a);
    w.chi = __half2half2(chi);
    w.clo = __float2half2_rn(clo);
    w.p   = __float2half2_rn(q * e);
    gh_rec[idx] = w;
}

__global__ void pack_sen_kernel(const float* __restrict__ smu,
                                const float* __restrict__ ssigma,
                                const float* __restrict__ sW,
                                const float* __restrict__ serev) {
    int idx = blockIdx.x * NN + threadIdx.x;   // i * NN + n
    float a = 0.5f * ssigma[idx];
    float m = smu[idx];
    float q = 0.5f * sW[idx];
    float e = serev[idx];
    g_senf[idx] = make_float4(a, -a * m, q * e, q);
}

__global__ void reduce_k_kernel(const float* __restrict__ W,
                                const float* __restrict__ erev,
                                const float* __restrict__ sW,
                                const float* __restrict__ serev,
                                const float* __restrict__ vleak,
                                const float* __restrict__ gleak,
                                const float* __restrict__ cm_t) {
    __shared__ float rp[128];
    __shared__ float rq[128];
    int n = blockIdx.x;
    int t = threadIdx.x;
    float sp = 0.0f, sq = 0.0f;
    for (int j = t; j < NN; j += 128) {
        float q = 0.5f * W[j * NN + n];
        sp += q * erev[j * NN + n];
        sq += q;
    }
    for (int i = t; i < NI; i += 128) {
        float q = 0.5f * sW[i * NN + n];
        sp += q * serev[i * NN + n];
        sq += q;
    }
    rp[t] = sp; rq[t] = sq;
    __syncthreads();
    for (int s = 64; s > 0; s >>= 1) {
        if (t < s) { rp[t] += rp[t + s]; rq[t] += rq[t + s]; }
        __syncthreads();
    }
    if (t == 0) {
        g_knum[n] = fmaf(gleak[n], vleak[n], rp[0]);
        g_kden[n] = cm_t[n] + gleak[n] + rq[0];
    }
}

// ---------------------------------------------------------------------------
// Main: 1 CTA/SM (GRID=128), 768 threads = 3 groups x 256. Thread owns output
// neuron n = tid&255; group g = tid>>8 reduces a third of the presynaptic
// range (j splits 88/84/84, CHUNK-aligned). 8 batch rows as 4 half2 pairs;
// one LDG.128 (weights) + one LDS.128 (state) per j serves all 4 pairs.
// Groups 1,2 write fp32 partials to smem; group 0 combines, divides, stores.
// Sensory pass, state, division, output all fp32.
// ---------------------------------------------------------------------------
__global__ __launch_bounds__(NT, 1) void liquid_main_kernel(
    const float* __restrict__ inputs,
    const float* __restrict__ state,
    const float* __restrict__ map_w,
    const float* __restrict__ map_b,
    const float* __restrict__ cm_t,
    float* __restrict__ out,
    int copies) {

    __shared__ float   sxf[NB][NI];                // mapped inputs (fp32)
    __shared__ alignas(16) __half2 sv2[NN][NPAIR]; // v state pairs: [j][pair]
    __shared__ float   pn1[NB][NN], pd1[NB][NN];   // group-1 partials
    __shared__ float   pn2[NB][NN], pd2[NB][NN];   // group-2 partials

    const int tid = threadIdx.x;
    const int n   = tid & (NN - 1);
    const int g   = tid >> 8;            // 0, 1 or 2
    const int r0  = blockIdx.x * NB;

    // j-range per group (CHUNK-aligned): 0..88, 88..172, 172..256
    const int jbs = (g == 0) ? 0 : (g == 1) ? 88 : 172;
    const int jes = (g == 0) ? 88 : (g == 1) ? 172 : 256;
    // i-range per group for the sensory pass: 0..44, 44..88, 88..128
    const int ibs = (g == 0) ? 0 : (g == 1) ? 44 : 88;
    const int ies = (g == 0) ? 44 : (g == 1) ? 88 : 128;

    // Load + map inputs (fp32)
    for (int idx = tid; idx < NB * NI; idx += NT) {
        int bb = idx >> 7;
        int i  = idx & (NI - 1);
        sxf[bb][i] = fmaf(inputs[(r0 + bb) * NI + i], map_w[i], map_b[i]);
    }
    // Load v state into half2 pairs: sv2[j][p] = (v[2p][j], v[2p+1][j])
    for (int idx = tid; idx < NN * NPAIR; idx += NT) {
        int j = idx >> 2;
        int p = idx & 3;
        sv2[j][p] = __floats2half2_rn(state[(r0 + 2 * p)     * NN + j],
                                      state[(r0 + 2 * p + 1) * NN + j]);
    }
    // fp32 state registers (group 0 uses them for cm*v and division)
    float vf[NB];
    #pragma unroll
    for (int bb = 0; bb < NB; bb++) vf[bb] = state[(r0 + bb) * NN + n];
    __syncthreads();

    const float cmn = cm_t[n];

    // ---- Sensory pass (fp32) ----
    float snum[NB], sden[NB];
    #pragma unroll
    for (int bb = 0; bb < NB; bb++) { snum[bb] = 0.0f; sden[bb] = 0.0f; }
    {
        #pragma unroll 2
        for (int ii = ibs; ii < ies; ii++) {
            float4 w = g_senf[ii * NN + n];
            #pragma unroll
            for (int bb = 0; bb < NB; bb++) {
                float z = fmaf(w.x, sxf[bb][ii], w.y);
                float t = tanh_fast(z);
                snum[bb] = fmaf(w.z, t, snum[bb]);
                sden[bb] = fmaf(w.w, t, sden[bb]);
            }
        }
    }
    if (g == 1) {
        #pragma unroll
        for (int bb = 0; bb < NB; bb++) { pn1[bb][n] = snum[bb]; pd1[bb][n] = sden[bb]; }
    } else if (g == 2) {
        #pragma unroll
        for (int bb = 0; bb < NB; bb++) { pn2[bb][n] = snum[bb]; pd2[bb][n] = sden[bb]; }
    }
    __syncthreads();
    if (g == 0) {
        const float kn = g_knum[n];
        const float kd = g_kden[n];
        #pragma unroll
        for (int bb = 0; bb < NB; bb++) {
            snum[bb] += pn1[bb][n] + pn2[bb][n] + kn;
            sden[bb] += pd1[bb][n] + pd2[bb][n] + kd;
        }
    }
    __syncthreads();   // partial buffers free for reuse

    // ---- Unfold loop (fp16x2 recurrent reduction, 4 pairs) ----
    for (int step = 0; step < UNFOLDS; step++) {
        float num[NB], den[NB];
        if (g == 0) {
            #pragma unroll
            for (int bb = 0; bb < NB; bb++) {
                num[bb] = fmaf(cmn, vf[bb], snum[bb]);
                den[bb] = sden[bb];
            }
        } else {
            #pragma unroll
            for (int bb = 0; bb < NB; bb++) { num[bb] = 0.0f; den[bb] = 0.0f; }
        }

        for (int j0 = jbs; j0 < jes; j0 += CHUNK) {
            __half2 hn[NPAIR], hd[NPAIR];
            #pragma unroll
            for (int p = 0; p < NPAIR; p++) {
                hn[p] = __float2half2_rn(0.0f);
                hd[p] = __float2half2_rn(0.0f);
            }
            #pragma unroll
            for (int cj = 0; cj < CHUNK; cj++) {
                int j = j0 + cj;
                uint4 u = *reinterpret_cast<const uint4*>(gh_rec + j * NN + n);
                __half2 wa = u2h(u.x), wchi = u2h(u.y), wclo = u2h(u.z), wp = u2h(u.w);
                __half2 wq = __habs2(wp);     // q = |p| since erev = +-1
                uint4 vv = *reinterpret_cast<const uint4*>(&sv2[j][0]);
                __half2 v0 = u2h(vv.x), v1 = u2h(vv.y), v2 = u2h(vv.z), v3 = u2h(vv.w);
                __half2 t;
                t = tanh2_fast(__hadd2(__hfma2(wa, v0, wchi), wclo));
                hn[0] = __hfma2(wp, t, hn[0]);  hd[0] = __hfma2(wq, t, hd[0]);
                t = tanh2_fast(__hadd2(__hfma2(wa, v1, wchi), wclo));
                hn[1] = __hfma2(wp, t, hn[1]);  hd[1] = __hfma2(wq, t, hd[1]);
                t = tanh2_fast(__hadd2(__hfma2(wa, v2, wchi), wclo));
                hn[2] = __hfma2(wp, t, hn[2]);  hd[2] = __hfma2(wq, t, hd[2]);
                t = tanh2_fast(__hadd2(__hfma2(wa, v3, wchi), wclo));
                hn[3] = __hfma2(wp, t, hn[3]);  hd[3] = __hfma2(wq, t, hd[3]);
            }
            #pragma unroll
            for (int p = 0; p < NPAIR; p++) {
                num[2 * p]     += __low2float(hn[p]);
                num[2 * p + 1] += __high2float(hn[p]);
                den[2 * p]     += __low2float(hd[p]);
                den[2 * p + 1] += __high2float(hd[p]);
            }
        }

        if (g == 1) {
            #pragma unroll
            for (int bb = 0; bb < NB; bb++) { pn1[bb][n] = num[bb]; pd1[bb][n] = den[bb]; }
        } else if (g == 2) {
            #pragma unroll
            for (int bb = 0; bb < NB; bb++) { pn2[bb][n] = num[bb]; pd2[bb][n] = den[bb]; }
        }
        __syncthreads();   // partials visible; all sv2 reads complete
        if (g == 0) {
            #pragma unroll
            for (int bb = 0; bb < NB; bb++) {
                float nu = num[bb] + pn1[bb][n] + pn2[bb][n];
                float de = den[bb] + pd1[bb][n] + pd2[bb][n];
                vf[bb] = __fdividef(nu, de);
            }
            sv2[n][0] = __floats2half2_rn(vf[0], vf[1]);
            sv2[n][1] = __floats2half2_rn(vf[2], vf[3]);
            sv2[n][2] = __floats2half2_rn(vf[4], vf[5]);
            sv2[n][3] = __floats2half2_rn(vf[6], vf[7]);
        }
        __syncthreads();
    }

    // ---- Output (reference returns (v, v) -> possibly 2 copies) ----
    if (g == 0) {
        #pragma unroll
        for (int bb = 0; bb < NB; bb++) {
            int row = r0 + bb;
            for (int c = 0; c < copies; c++)
                out[c * (BATCH * NN) + row * NN + n] = vf[bb];
        }
    }
}

// ---------------------------------------------------------------------------
extern "C" void kernel_launch(void* const* d_in, const int* in_sizes, int n_in,
                              void* d_out, int out_size) {
    const float* inputs = (const float*)d_in[0];
    const float* state  = (const float*)d_in[1];
    const float* map_w  = (const float*)d_in[2];
    const float* map_b  = (const float*)d_in[3];
    const float* smu    = (const float*)d_in[4];
    const float* ssig   = (const float*)d_in[5];
    const float* sW     = (const float*)d_in[6];
    const float* serev  = (const float*)d_in[7];
    const float* mu     = (const float*)d_in[8];
    const float* sigma  = (const float*)d_in[9];
    const float* W      = (const float*)d_in[10];
    const float* erev   = (const float*)d_in[11];
    const float* vleak  = (const float*)d_in[12];
    const float* gleak  = (const float*)d_in[13];
    const float* cm     = (const float*)d_in[14];

    int copies = out_size / (BATCH * NN);
    if (copies < 1) copies = 1;

    pack_rec_kernel<<<NN, NN>>>(mu, sigma, W, erev);
    pack_sen_kernel<<<NI, NN>>>(smu, ssig, sW, serev);
    reduce_k_kernel<<<NN, 128>>>(W, erev, sW, serev, vleak, gleak, cm);
    liquid_main_kernel<<<GRID, NT>>>(inputs, state, map_w, map_b, cm,
                                     (float*)d_out, copies);
}

// round 14
// speedup vs baseline: 1.2838x; 1.2082x over previous
#include <cuda_runtime.h>

#define NN      256     // neurons (post)
#define NI      128     // sensory inputs
#define BATCH   1024
#define UNFOLDS 6
#define NB      7       // batch rows per CTA (147 CTAs * 7 = 1029 >= 1024)
#define GRID    147
#define NT      768     // 3 groups of 256; group g reduces ~1/3 of the pre range

// Packed weights: (a = sigma/2, c = -sigma*mu/2, P = W*erev/2, Q = W/2)
// sigmoid(sigma*(v-mu)) = 0.5 + 0.5*tanh( (sigma/2)*v - (sigma*mu/2) )
// Constant halves of W*sig*erev / W*sig folded into g_knum/g_kden per n.
__device__ float4 g_rec[NN * NN];   // recurrent, [pre j][post n]
__device__ float4 g_sen[NI * NN];   // sensory,   [pre i][post n]
__device__ float  g_knum[NN];       // gleak*vleak + sum over pre of P
__device__ float  g_kden[NN];       // cm + gleak + sum over pre of Q

__device__ __forceinline__ float tanh_fast(float x) {
    float y;
    asm("tanh.approx.f32 %0, %1;" : "=f"(y) : "f"(x));
    return y;
}

// ---------------------------------------------------------------------------
// Prep kernels
// ---------------------------------------------------------------------------
__global__ void pack_rec_kernel(const float* __restrict__ mu,
                                const float* __restrict__ sigma,
                                const float* __restrict__ W,
                                const float* __restrict__ erev) {
    int idx = blockIdx.x * NN + threadIdx.x;   // j * NN + n
    float a = 0.5f * sigma[idx];
    float m = mu[idx];
    float q = 0.5f * W[idx];
    float e = erev[idx];
    g_rec[idx] = make_float4(a, -a * m, q * e, q);
}

__global__ void pack_sen_kernel(const float* __restrict__ smu,
                                const float* __restrict__ ssigma,
                                const float* __restrict__ sW,
                                const float* __restrict__ serev) {
    int idx = blockIdx.x * NN + threadIdx.x;   // i * NN + n
    float a = 0.5f * ssigma[idx];
    float m = smu[idx];
    float q = 0.5f * sW[idx];
    float e = serev[idx];
    g_sen[idx] = make_float4(a, -a * m, q * e, q);
}

__global__ void reduce_k_kernel(const float* __restrict__ W,
                                const float* __restrict__ erev,
                                const float* __restrict__ sW,
                                const float* __restrict__ serev,
                                const float* __restrict__ vleak,
                                const float* __restrict__ gleak,
                                const float* __restrict__ cm_t) {
    __shared__ float rp[128];
    __shared__ float rq[128];
    int n = blockIdx.x;
    int t = threadIdx.x;
    float sp = 0.0f, sq = 0.0f;
    for (int j = t; j < NN; j += 128) {
        float q = 0.5f * W[j * NN + n];
        sp += q * erev[j * NN + n];
        sq += q;
    }
    for (int i = t; i < NI; i += 128) {
        float q = 0.5f * sW[i * NN + n];
        sp += q * serev[i * NN + n];
        sq += q;
    }
    rp[t] = sp; rq[t] = sq;
    __syncthreads();
    for (int s = 64; s > 0; s >>= 1) {
        if (t < s) { rp[t] += rp[t + s]; rq[t] += rq[t + s]; }
        __syncthreads();
    }
    if (t == 0) {
        g_knum[n] = fmaf(gleak[n], vleak[n], rp[0]);
        g_kden[n] = cm_t[n] + gleak[n] + rq[0];
    }
}

// ---------------------------------------------------------------------------
// Main: 1 CTA/SM (GRID=147), 768 threads = 3 groups x 256. Thread owns output
// neuron n = tid&255; group g = tid>>8 reduces ~1/3 of the presynaptic range
// (j split 88/84/84). Groups 1,2 write fp32 partials to smem; group 0
// combines, divides, stores state. All fp32.
// ---------------------------------------------------------------------------
__global__ __launch_bounds__(NT, 1) void liquid_main_kernel(
    const float* __restrict__ inputs,
    const float* __restrict__ state,
    const float* __restrict__ map_w,
    const float* __restrict__ map_b,
    const float* __restrict__ cm_t,
    float* __restrict__ out,
    int copies) {

    __shared__ float sx[NB][NI];               // mapped inputs
    __shared__ float sv[NB][NN];               // current v state
    __shared__ float pn1[NB][NN], pd1[NB][NN]; // group-1 partials
    __shared__ float pn2[NB][NN], pd2[NB][NN]; // group-2 partials

    const int tid = threadIdx.x;
    const int n   = tid & (NN - 1);
    const int g   = tid >> 8;        // 0, 1 or 2
    const int r0  = blockIdx.x * NB;

    // j-range per group (multiples of 4): 0..88, 88..172, 172..256
    const int jbs = (g == 0) ? 0 : (g == 1) ? 88 : 172;
    const int jes = (g == 0) ? 88 : (g == 1) ? 172 : 256;
    // i-range per group: 0..44, 44..88, 88..128
    const int ibs = (g == 0) ? 0 : (g == 1) ? 44 : 88;
    const int ies = (g == 0) ? 44 : (g == 1) ? 88 : 128;

    // Load + map inputs (x = inputs*map_w + map_b)
    for (int idx = tid; idx < NB * NI; idx += NT) {
        int bb  = idx >> 7;
        int i   = idx & (NI - 1);
        int row = r0 + bb; if (row > BATCH - 1) row = BATCH - 1;
        sx[bb][i] = fmaf(inputs[row * NI + i], map_w[i], map_b[i]);
    }
    // Load v state
    for (int idx = tid; idx < NB * NN; idx += NT) {
        int bb  = idx >> 8;
        int i   = idx & (NN - 1);
        int row = r0 + bb; if (row > BATCH - 1) row = BATCH - 1;
        sv[bb][i] = state[row * NN + i];
    }
    __syncthreads();

    // ---- Sensory pass: group g reduces i in [ibs, ies) ----
    float snum[NB], sden[NB];
    #pragma unroll
    for (int bb = 0; bb < NB; bb++) { snum[bb] = 0.0f; sden[bb] = 0.0f; }

    #pragma unroll 4
    for (int i = ibs; i < ies; i++) {
        float4 w = g_sen[i * NN + n];
        #pragma unroll
        for (int bb = 0; bb < NB; bb++) {
            float z = fmaf(w.x, sx[bb][i], w.y);
            float t = tanh_fast(z);
            snum[bb] = fmaf(w.z, t, snum[bb]);
            sden[bb] = fmaf(w.w, t, sden[bb]);
        }
    }
    if (g == 1) {
        #pragma unroll
        for (int bb = 0; bb < NB; bb++) { pn1[bb][n] = snum[bb]; pd1[bb][n] = sden[bb]; }
    } else if (g == 2) {
        #pragma unroll
        for (int bb = 0; bb < NB; bb++) { pn2[bb][n] = snum[bb]; pd2[bb][n] = sden[bb]; }
    }
    __syncthreads();

    const float cm = cm_t[n];
    if (g == 0) {
        const float kn = g_knum[n];
        const float kd = g_kden[n];
        #pragma unroll
        for (int bb = 0; bb < NB; bb++) {
            snum[bb] += pn1[bb][n] + pn2[bb][n] + kn;
            sden[bb] += pd1[bb][n] + pd2[bb][n] + kd;
        }
    }
    __syncthreads();   // partial buffers free for reuse in the step loop

    // ---- Unfold loop ----
    for (int step = 0; step < UNFOLDS; step++) {
        float num[NB], den[NB];
        if (g == 0) {
            #pragma unroll
            for (int bb = 0; bb < NB; bb++) {
                num[bb] = fmaf(cm, sv[bb][n], snum[bb]);
                den[bb] = sden[bb];
            }
        } else {
            #pragma unroll
            for (int bb = 0; bb < NB; bb++) { num[bb] = 0.0f; den[bb] = 0.0f; }
        }

        #pragma unroll 4
        for (int j = jbs; j < jes; j++) {
            float4 w = g_rec[j * NN + n];
            #pragma unroll
            for (int bb = 0; bb < NB; bb++) {
                float z = fmaf(w.x, sv[bb][j], w.y);
                float t = tanh_fast(z);
                num[bb] = fmaf(w.z, t, num[bb]);
                den[bb] = fmaf(w.w, t, den[bb]);
            }
        }

        if (g == 1) {
            #pragma unroll
            for (int bb = 0; bb < NB; bb++) { pn1[bb][n] = num[bb]; pd1[bb][n] = den[bb]; }
        } else if (g == 2) {
            #pragma unroll
            for (int bb = 0; bb < NB; bb++) { pn2[bb][n] = num[bb]; pd2[bb][n] = den[bb]; }
        }
        __syncthreads();   // partials visible; all sv reads complete
        if (g == 0) {
            #pragma unroll
            for (int bb = 0; bb < NB; bb++) {
                float nu = num[bb] + pn1[bb][n] + pn2[bb][n];
                float de = den[bb] + pd1[bb][n] + pd2[bb][n];
                sv[bb][n] = __fdividef(nu, de);
            }
        }
        __syncthreads();
    }

    // ---- Output (reference returns (v, v) -> possibly 2 copies) ----
    // Group g writes copy g when copies > 1; otherwise group 0 writes.
    #pragma unroll
    for (int bb = 0; bb < NB; bb++) {
        int row = r0 + bb;
        if (row >= BATCH) continue;
        float v = sv[bb][n];
        if (copies > 1) {
            if (g < copies) out[g * (BATCH * NN) + row * NN + n] = v;
        } else if (g == 0) {
            out[row * NN + n] = v;
        }
    }
}

// ---------------------------------------------------------------------------
extern "C" void kernel_launch(void* const* d_in, const int* in_sizes, int n_in,
                              void* d_out, int out_size) {
    const float* inputs = (const float*)d_in[0];
    const float* state  = (const float*)d_in[1];
    const float* map_w  = (const float*)d_in[2];
    const float* map_b  = (const float*)d_in[3];
    const float* smu    = (const float*)d_in[4];
    const float* ssig   = (const float*)d_in[5];
    const float* sW     = (const float*)d_in[6];
    const float* serev  = (const float*)d_in[7];
    const float* mu     = (const float*)d_in[8];
    const float* sigma  = (const float*)d_in[9];
    const float* W      = (const float*)d_in[10];
    const float* erev   = (const float*)d_in[11];
    const float* vleak  = (const float*)d_in[12];
    const float* gleak  = (const float*)d_in[13];
    const float* cm     = (const float*)d_in[14];

    int copies = out_size / (BATCH * NN);
    if (copies < 1) copies = 1;

    pack_rec_kernel<<<NN, NN>>>(mu, sigma, W, erev);
    pack_sen_kernel<<<NI, NN>>>(smu, ssig, sW, serev);
    reduce_k_kernel<<<NN, 128>>>(W, erev, sW, serev, vleak, gleak, cm);
    liquid_main_kernel<<<GRID, NT>>>(inputs, state, map_w, map_b, cm,
                                     (float*)d_out, copies);
}